// round 13
// baseline (speedup 1.0000x reference)
#include <cuda_runtime.h>
#include <cstdint>
#include <cstddef>

namespace cfg {
constexpr int T  = 128;
constexpr int E  = 256;
constexpr int H  = 64;

constexpr int A0HI_B = 0;        // 32 KB
constexpr int A0LO_B = 32768;    // 32 KB
constexpr int A1HI_B = 65536;    // 32 KB
constexpr int A1LO_B = 98304;    // 32 KB
constexpr int B0HI_B = 131072;   // 48 KB
constexpr int B1HI_B = 180224;   // 48 KB -> 229376
constexpr int SMEM_BYTES = 229376;

constexpr int QHI_B = 0;
constexpr int QLO_B = 16384;
constexpr int KHI_B = 32768;
constexpr int VHI_B = 49152;     // ends 65536

constexpr int REDM_B  = 65536;   // 2 x 128 fp32 row maxima
constexpr int REDS_B  = 66560;   // 2 x 128 fp32 row sums
constexpr int OPART_B = 67584;   // 128 x OP_STRIDE fp32 partial O
constexpr int OP_STRIDE = 68;
}

__device__ __align__(16) unsigned char g_Wh[2 * 49152];

// ---------------------------------------------------------------------------
static __device__ __forceinline__ uint32_t smem_u32(const void* p) {
    uint32_t a;
    asm("{ .reg .u64 t; cvta.to.shared.u64 t, %1; cvt.u32.u64 %0, t; }" : "=r"(a) : "l"(p));
    return a;
}
static __device__ __forceinline__ uint32_t pkh(float f0, float f1) {
    uint32_t r;
    asm("cvt.rn.f16x2.f32 %0, %1, %2;" : "=r"(r) : "f"(f1), "f"(f0));
    return r;
}
static __device__ __forceinline__ void split2h(float f0, float f1, uint32_t& h, uint32_t& l) {
    h = pkh(f0, f1);
    float g0, g1;
    asm("{.reg .b16 a,b;\n\t mov.b32 {a,b}, %2;\n\t cvt.f32.f16 %0, a;\n\t cvt.f32.f16 %1, b;}"
        : "=f"(g0), "=f"(g1) : "r"(h));
    l = pkh(f0 - g0, f1 - g1);
}
static __device__ __forceinline__ void ldsm4(uint32_t r[4], uint32_t addr) {
    asm volatile("ldmatrix.sync.aligned.m8n8.x4.shared.b16 {%0,%1,%2,%3}, [%4];"
                 : "=r"(r[0]), "=r"(r[1]), "=r"(r[2]), "=r"(r[3]) : "r"(addr));
}
static __device__ __forceinline__ void ldsm4t(uint32_t r[4], uint32_t addr) {
    asm volatile("ldmatrix.sync.aligned.m8n8.x4.trans.shared.b16 {%0,%1,%2,%3}, [%4];"
                 : "=r"(r[0]), "=r"(r[1]), "=r"(r[2]), "=r"(r[3]) : "r"(addr));
}
static __device__ __forceinline__ void mma16816(float d[4],
                                                const uint32_t a[4],
                                                uint32_t b0, uint32_t b1) {
    asm volatile(
        "mma.sync.aligned.m16n8k16.row.col.f32.f16.f16.f32 "
        "{%0,%1,%2,%3}, {%4,%5,%6,%7}, {%8,%9}, {%0,%1,%2,%3};"
        : "+f"(d[0]), "+f"(d[1]), "+f"(d[2]), "+f"(d[3])
        : "r"(a[0]), "r"(a[1]), "r"(a[2]), "r"(a[3]), "r"(b0), "r"(b1));
}
#define CP16(dst, src) \
    asm volatile("cp.async.cg.shared.global [%0], [%1], 16;" :: "r"(dst), "l"(src) : "memory")
#define CPCOMMIT() asm volatile("cp.async.commit_group;" ::: "memory")
#define CPWAIT(n)  asm volatile("cp.async.wait_group %0;" :: "n"(n) : "memory")

// ---------------------------------------------------------------------------
__global__ void build_w_images(const float* __restrict__ Wq,
                               const float* __restrict__ Wk,
                               const float* __restrict__ Wv)
{
    int gid = blockIdx.x * blockDim.x + threadIdx.x;
    int c   = gid / 3072;
    int u   = gid % 3072;
    int n   = u >> 4;
    int j   = u & 15;
    int k0  = c * 128 + j * 8;

    const float* Wsrc = (n < 64) ? (Wq + n) : (n < 128) ? (Wk + n - 64) : (Wv + n - 128);
    float f[8];
    #pragma unroll
    for (int e = 0; e < 8; ++e) f[e] = Wsrc[(size_t)(k0 + e) * cfg::H];

    uint32_t h[4];
    #pragma unroll
    for (int p = 0; p < 4; ++p) h[p] = pkh(f[2 * p], f[2 * p + 1]);

    size_t off = (size_t)c * 49152 + (size_t)n * 256 + (size_t)((j ^ (n & 7)) << 4);
    *(uint4*)(g_Wh + off) = make_uint4(h[0], h[1], h[2], h[3]);
}

// ---------------------------------------------------------------------------
__global__ __launch_bounds__(512, 1)
void attn_head_kernel(const float* __restrict__ x,
                      float* __restrict__ out)
{
    using namespace cfg;
    extern __shared__ __align__(1024) unsigned char smraw[];
    unsigned char* smc = smraw;
    float*         smp = (float*)smraw;

    const int tid = threadIdx.x;
    const int wid = tid >> 5;
    const int lid = tid & 31;
    const int b   = blockIdx.x;
    const uint32_t sb = smem_u32(smraw);
    const float* xb = x + (size_t)b * (T * E);

    // ===== async W copies (both chunks) =====
    #pragma unroll
    for (int i = 0; i < 6; ++i) {
        int u = i * 512 + tid;
        CP16(sb + B0HI_B + u * 16, g_Wh + u * 16);
    }
    CPCOMMIT();
    #pragma unroll
    for (int i = 0; i < 6; ++i) {
        int u = i * 512 + tid;
        CP16(sb + B1HI_B + u * 16, g_Wh + 49152 + u * 16);
    }
    CPCOMMIT();

    // ===== x chunk 0 -> A0 hi/lo =====
    #pragma unroll
    for (int i = 0; i < 4; ++i) {
        int u   = i * 512 + tid;
        int row = u >> 4;
        int j   = u & 15;
        const float4* src = (const float4*)(xb + (size_t)row * E + j * 8);
        float4 fa = src[0], fb = src[1];
        uint32_t h0, h1, h2, h3, l0, l1, l2, l3;
        split2h(fa.x, fa.y, h0, l0);
        split2h(fa.z, fa.w, h1, l1);
        split2h(fb.x, fb.y, h2, l2);
        split2h(fb.z, fb.w, h3, l3);
        int off = row * 256 + ((j ^ (row & 7)) << 4);
        *(uint4*)(smc + A0HI_B + off) = make_uint4(h0, h1, h2, h3);
        *(uint4*)(smc + A0LO_B + off) = make_uint4(l0, l1, l2, l3);
    }
    CPWAIT(1);
    __syncthreads();

    // ===== Warp-tile constants: 4x4 grid, tile 32x48 =====
    const int mbase = (wid >> 2) * 32;
    const int nbase = (wid & 3) * 48;
    const int arow  = mbase + (lid & 7) + ((lid >> 3) & 1) * 8;
    const int axor  = arow & 7;
    const int ajsel = (lid >> 4) & 1;
    const int brow  = nbase + (lid & 7) + ((lid >> 4) & 1) * 8;
    const int bxor  = brow & 7;
    const int bjsel = (lid >> 3) & 1;

    float acc[2][6][4];
    #pragma unroll
    for (int mt = 0; mt < 2; ++mt)
        #pragma unroll
        for (int nt = 0; nt < 6; ++nt)
            #pragma unroll
            for (int r = 0; r < 4; ++r) acc[mt][nt][r] = 0.f;

    // One k16-step: all loads first, then 12 independent hi MMAs, then 12 lo.
    auto kstep = [&](uint32_t aHi, uint32_t aLo, uint32_t bB, int s) {
        const uint32_t aoff = (uint32_t)(((2 * s + ajsel) ^ axor) << 4);
        const uint32_t boff = (uint32_t)(((2 * s + bjsel) ^ bxor) << 4);
        uint32_t ah[2][4], al[2][4], bh[3][4];
        ldsm4(ah[0], aHi + aoff);
        ldsm4(ah[1], aHi + 16 * 256 + aoff);
        ldsm4(bh[0], bB + boff);
        ldsm4(bh[1], bB + 16 * 256 + boff);
        ldsm4(bh[2], bB + 32 * 256 + boff);
        ldsm4(al[0], aLo + aoff);
        ldsm4(al[1], aLo + 16 * 256 + aoff);
        #pragma unroll
        for (int g = 0; g < 3; ++g)
            #pragma unroll
            for (int mt = 0; mt < 2; ++mt)
                #pragma unroll
                for (int nn = 0; nn < 2; ++nn)
                    mma16816(acc[mt][g * 2 + nn], ah[mt], bh[g][2 * nn], bh[g][2 * nn + 1]);
        #pragma unroll
        for (int g = 0; g < 3; ++g)
            #pragma unroll
            for (int mt = 0; mt < 2; ++mt)
                #pragma unroll
                for (int nn = 0; nn < 2; ++nn)
                    mma16816(acc[mt][g * 2 + nn], al[mt], bh[g][2 * nn], bh[g][2 * nn + 1]);
    };

    const uint32_t a0h = sb + A0HI_B + arow * 256;
    const uint32_t a0l = sb + A0LO_B + arow * 256;
    const uint32_t a1h = sb + A1HI_B + arow * 256;
    const uint32_t a1l = sb + A1LO_B + arow * 256;
    const uint32_t b0  = sb + B0HI_B + brow * 256;
    const uint32_t b1  = sb + B1HI_B + brow * 256;

    // ===== MMA chunk 0, x chunk-1 convert pipelined on even k-steps =====
    float4 p0, p1;
    {
        int row = tid >> 4, j = tid & 15;
        const float4* src = (const float4*)(xb + (size_t)row * E + 128 + j * 8);
        p0 = src[0]; p1 = src[1];
    }
    #pragma unroll 1
    for (int s = 0; s < 8; ++s) {
        kstep(a0h, a0l, b0, s);
        if ((s & 1) == 0) {
            int i = s >> 1;
            int u = i * 512 + tid;
            int row = u >> 4, j = u & 15;
            uint32_t h0, h1, h2, h3, l0, l1, l2, l3;
            split2h(p0.x, p0.y, h0, l0);
            split2h(p0.z, p0.w, h1, l1);
            split2h(p1.x, p1.y, h2, l2);
            split2h(p1.z, p1.w, h3, l3);
            int off = row * 256 + ((j ^ (row & 7)) << 4);
            *(uint4*)(smc + A1HI_B + off) = make_uint4(h0, h1, h2, h3);
            *(uint4*)(smc + A1LO_B + off) = make_uint4(l0, l1, l2, l3);
            if (i < 3) {
                int u2 = (i + 1) * 512 + tid;
                int r2 = u2 >> 4, j2 = u2 & 15;
                const float4* src = (const float4*)(xb + (size_t)r2 * E + 128 + j2 * 8);
                p0 = src[0]; p1 = src[1];
            }
        }
    }
    CPWAIT(0);
    __syncthreads();

    // ===== MMA chunk 1 =====
    #pragma unroll 1
    for (int s = 0; s < 8; ++s) kstep(a1h, a1l, b1, s);
    __syncthreads();

    // ===== Epilogue: fragments -> fp16 images (Q hi+lo scaled 1/8; K,V hi) =====
    {
        const int r0 = lid >> 2;
        const int c4 = lid & 3;
        #pragma unroll
        for (int mt = 0; mt < 2; ++mt) {
            #pragma unroll
            for (int nt = 0; nt < 6; ++nt) {
                int n = nbase + 8 * nt;
                int row = mbase + mt * 16 + r0;
                int rw8 = row + 8;
                if (n < 64) {
                    int u = n >> 3;
                    uint32_t h0, l0, h1, l1;
                    split2h(0.125f * acc[mt][nt][0], 0.125f * acc[mt][nt][1], h0, l0);
                    split2h(0.125f * acc[mt][nt][2], 0.125f * acc[mt][nt][3], h1, l1);
                    int byt0 = row * 128 + ((u ^ (row & 7)) << 4) + c4 * 4;
                    int byt1 = rw8 * 128 + ((u ^ (rw8 & 7)) << 4) + c4 * 4;
                    *(uint32_t*)(smc + QHI_B + byt0) = h0;
                    *(uint32_t*)(smc + QLO_B + byt0) = l0;
                    *(uint32_t*)(smc + QHI_B + byt1) = h1;
                    *(uint32_t*)(smc + QLO_B + byt1) = l1;
                } else {
                    int hiB = (n < 128) ? KHI_B : VHI_B;
                    int m   = (n < 128) ? n - 64 : n - 128;
                    int u   = m >> 3;
                    uint32_t h0 = pkh(acc[mt][nt][0], acc[mt][nt][1]);
                    uint32_t h1 = pkh(acc[mt][nt][2], acc[mt][nt][3]);
                    int byt0 = row * 128 + ((u ^ (row & 7)) << 4) + c4 * 4;
                    int byt1 = rw8 * 128 + ((u ^ (rw8 & 7)) << 4) + c4 * 4;
                    *(uint32_t*)(smc + hiB + byt0) = h0;
                    *(uint32_t*)(smc + hiB + byt1) = h1;
                }
            }
        }
    }
    __syncthreads();

    // ===== Phase 2: attention; pair (pr, mem) shares stripe qs =====
    const int pr  = wid & 7;
    const int mem = wid >> 3;
    const int qs  = (pr < 4) ? pr : 11 - pr;
    const int rw  = qs * 16;
    const int rofsA = (lid & 7) + ((lid >> 3) & 1) * 8;
    const int jselA = (lid >> 4) & 1;
    const int rofsK = (lid & 7) + ((lid >> 4) & 1) * 8;
    const int jselK = (lid >> 3) & 1;
    const int xorr  = lid & 7;
    const int vub   = (lid >> 4) & 1;

    uint32_t qh[4][4], ql[4][4];
    #pragma unroll
    for (int s = 0; s < 4; ++s) {
        uint32_t off = (uint32_t)((rw + rofsA) * 128 + (((2 * s + jselA) ^ xorr) << 4));
        ldsm4(qh[s], sb + QHI_B + off);
        ldsm4(ql[s], sb + QLO_B + off);
    }

    float sacc[4][2][4];
    #pragma unroll
    for (int it = 0; it < 4; ++it)
        #pragma unroll
        for (int nn = 0; nn < 2; ++nn)
            #pragma unroll
            for (int i = 0; i < 4; ++i) sacc[it][nn][i] = 0.f;

    // S loop: s-outer; per s load kh for all live blocks, then hi-all, lo-all.
    #pragma unroll
    for (int s = 0; s < 4; ++s) {
        uint32_t kh[4][4];
        #pragma unroll
        for (int it = 0; it < 4; ++it) {
            int pb = 2 * it + mem;
            if (pb <= qs) {
                uint32_t off = (uint32_t)((16 * pb + rofsK) * 128 +
                                          (((2 * s + jselK) ^ xorr) << 4));
                ldsm4(kh[it], sb + KHI_B + off);
            }
        }
        #pragma unroll
        for (int it = 0; it < 4; ++it) {
            int pb = 2 * it + mem;
            if (pb <= qs)
                #pragma unroll
                for (int nn = 0; nn < 2; ++nn)
                    mma16816(sacc[it][nn], qh[s], kh[it][2 * nn], kh[it][2 * nn + 1]);
        }
        #pragma unroll
        for (int it = 0; it < 4; ++it) {
            int pb = 2 * it + mem;
            if (pb <= qs)
                #pragma unroll
                for (int nn = 0; nn < 2; ++nn)
                    mma16816(sacc[it][nn], ql[s], kh[it][2 * nn], kh[it][2 * nn + 1]);
        }
    }

    const int r0   = lid >> 2;
    const int cq   = (lid & 3) * 2;
    const int rowh = rw + r0;
    const int rowl = rowh + 8;
    float* redm = smp + (REDM_B >> 2);
    float* reds = smp + (REDS_B >> 2);
    float* opar = smp + (OPART_B >> 2);

    float m0 = -1e30f, m1 = -1e30f;
    #pragma unroll
    for (int it = 0; it < 4; ++it) {
        int pb = 2 * it + mem;
        if (pb <= qs) {
            #pragma unroll
            for (int nn = 0; nn < 2; ++nn) {
                if (pb == qs) {
                    int colb = 16 * pb + 8 * nn + cq;
                    if (colb     > rowh) sacc[it][nn][0] = -1e30f;
                    if (colb + 1 > rowh) sacc[it][nn][1] = -1e30f;
                    if (colb     > rowl) sacc[it][nn][2] = -1e30f;
                    if (colb + 1 > rowl) sacc[it][nn][3] = -1e30f;
                }
                m0 = fmaxf(m0, fmaxf(sacc[it][nn][0], sacc[it][nn][1]));
                m1 = fmaxf(m1, fmaxf(sacc[it][nn][2], sacc[it][nn][3]));
            }
        }
    }
    m0 = fmaxf(m0, __shfl_xor_sync(0xffffffffu, m0, 1));
    m0 = fmaxf(m0, __shfl_xor_sync(0xffffffffu, m0, 2));
    m1 = fmaxf(m1, __shfl_xor_sync(0xffffffffu, m1, 1));
    m1 = fmaxf(m1, __shfl_xor_sync(0xffffffffu, m1, 2));
    if ((lid & 3) == 0) {
        redm[mem * 128 + rowh] = m0;
        redm[mem * 128 + rowl] = m1;
    }
    __syncthreads();
    const float mx0 = fmaxf(redm[rowh], redm[128 + rowh]);
    const float mx1 = fmaxf(redm[rowl], redm[128 + rowl]);

    float s0 = 0.f, s1 = 0.f;
    #pragma unroll
    for (int it = 0; it < 4; ++it) {
        int pb = 2 * it + mem;
        if (pb <= qs) {
            #pragma unroll
            for (int nn = 0; nn < 2; ++nn) {
                sacc[it][nn][0] = __expf(sacc[it][nn][0] - mx0);
                sacc[it][nn][1] = __expf(sacc[it][nn][1] - mx0);
                sacc[it][nn][2] = __expf(sacc[it][nn][2] - mx1);
                sacc[it][nn][3] = __expf(sacc[it][nn][3] - mx1);
                s0 += sacc[it][nn][0] + sacc[it][nn][1];
                s1 += sacc[it][nn][2] + sacc[it][nn][3];
            }
        }
    }
    s0 += __shfl_xor_sync(0xffffffffu, s0, 1);
    s0 += __shfl_xor_sync(0xffffffffu, s0, 2);
    s1 += __shfl_xor_sync(0xffffffffu, s1, 1);
    s1 += __shfl_xor_sync(0xffffffffu, s1, 2);
    if ((lid & 3) == 0) {
        reds[mem * 128 + rowh] = s0;
        reds[mem * 128 + rowl] = s1;
    }

    uint32_t ph[4][4], pl[4][4];
    #pragma unroll
    for (int it = 0; it < 4; ++it) {
        int pb = 2 * it + mem;
        if (pb <= qs) {
            split2h(sacc[it][0][0], sacc[it][0][1], ph[it][0], pl[it][0]);
            split2h(sacc[it][0][2], sacc[it][0][3], ph[it][1], pl[it][1]);
            split2h(sacc[it][1][0], sacc[it][1][1], ph[it][2], pl[it][2]);
            split2h(sacc[it][1][2], sacc[it][1][3], ph[it][3], pl[it][3]);
        }
    }

    float oacc[8][4];
    #pragma unroll
    for (int nb = 0; nb < 8; ++nb)
        #pragma unroll
        for (int i = 0; i < 4; ++i) oacc[nb][i] = 0.f;

    // PV loop: per block, all 4 vh loads first, then 8 hi MMAs, then 8 lo.
    #pragma unroll
    for (int it = 0; it < 4; ++it) {
        int pb = 2 * it + mem;
        if (pb <= qs) {
            uint32_t vh[4][4];
            #pragma unroll
            for (int cg = 0; cg < 4; ++cg) {
                uint32_t off = (uint32_t)((16 * pb + rofsA) * 128 +
                                          (((2 * cg + vub) ^ xorr) << 4));
                ldsm4t(vh[cg], sb + VHI_B + off);
            }
            #pragma unroll
            for (int cg = 0; cg < 4; ++cg)
                #pragma unroll
                for (int nn = 0; nn < 2; ++nn)
                    mma16816(oacc[2 * cg + nn], ph[it], vh[cg][2 * nn], vh[cg][2 * nn + 1]);
            #pragma unroll
            for (int cg = 0; cg < 4; ++cg)
                #pragma unroll
                for (int nn = 0; nn < 2; ++nn)
                    mma16816(oacc[2 * cg + nn], pl[it], vh[cg][2 * nn], vh[cg][2 * nn + 1]);
        }
    }

    if (mem == 0) {
        #pragma unroll
        for (int nb = 0; nb < 8; ++nb) {
            int col = 8 * nb + cq;
            float2 v0; v0.x = oacc[nb][0]; v0.y = oacc[nb][1];
            float2 v1; v1.x = oacc[nb][2]; v1.y = oacc[nb][3];
            *(float2*)(opar + rowh * OP_STRIDE + col) = v0;
            *(float2*)(opar + rowl * OP_STRIDE + col) = v1;
        }
    }
    __syncthreads();
    if (mem == 1) {
        const float inv0 = 1.f / (reds[rowh] + reds[128 + rowh]);
        const float inv1 = 1.f / (reds[rowl] + reds[128 + rowl]);
        float* ob = out + (size_t)b * T * H;
        #pragma unroll
        for (int nb = 0; nb < 8; ++nb) {
            int col = 8 * nb + cq;
            float2 u0 = *(float2*)(opar + rowh * OP_STRIDE + col);
            float2 u1 = *(float2*)(opar + rowl * OP_STRIDE + col);
            float2 v0; v0.x = (oacc[nb][0] + u0.x) * inv0; v0.y = (oacc[nb][1] + u0.y) * inv0;
            float2 v1; v1.x = (oacc[nb][2] + u1.x) * inv1; v1.y = (oacc[nb][3] + u1.y) * inv1;
            *(float2*)(ob + rowh * H + col) = v0;
            *(float2*)(ob + rowl * H + col) = v1;
        }
    }
}

// ---------------------------------------------------------------------------
extern "C" void kernel_launch(void* const* d_in, const int* in_sizes, int n_in,
                              void* d_out, int out_size)
{
    using namespace cfg;
    const float* x  = (const float*)d_in[0];
    const float* Wq = (const float*)d_in[1];
    const float* Wk = (const float*)d_in[2];
    const float* Wv = (const float*)d_in[3];
    float* out = (float*)d_out;

    const int B = in_sizes[0] / (T * E);

    build_w_images<<<24, 256>>>(Wq, Wk, Wv);

    cudaFuncSetAttribute(attn_head_kernel,
                         cudaFuncAttributeMaxDynamicSharedMemorySize, SMEM_BYTES);
    attn_head_kernel<<<B, 512, SMEM_BYTES>>>(x, out);
}

// round 14
// speedup vs baseline: 1.3529x; 1.3529x over previous
#include <cuda_runtime.h>
#include <cstdint>
#include <cstddef>

namespace cfg {
constexpr int T  = 128;
constexpr int E  = 256;
constexpr int H  = 64;

// GEMM smem (bytes). A rows: 256B = 128 fp16 (one 128-k chunk), 16B units
// xor-swizzled by (row&7). x is 1-term (hi only); W hi only.
constexpr int A0HI_B = 0;        // 32 KB
constexpr int A1HI_B = 32768;    // 32 KB
constexpr int XRAW_B = 65536;    // 64 KB raw fp32 x chunk0 of NEXT batch
constexpr int B0HI_B = 131072;   // 48 KB
constexpr int B1HI_B = 180224;   // 48 KB -> 229376
constexpr int SMEM_BYTES = 229376;

// Attention images overlay A/XRAW region post-GEMM:
// [128 rows][64 fp16 = 128B], 16B units xor-swizzled by (row&7).
constexpr int QHI_B = 0;
constexpr int QLO_B = 16384;
constexpr int KHI_B = 32768;
constexpr int VHI_B = 49152;     // ends 65536

// Scratch overlays the dead Q-image region (written only after the
// post-S barrier, when all warps are done reading Q and K).
constexpr int REDM_B  = 0;       // 2 x 128 fp32 row maxima (1 KB)
constexpr int REDS_B  = 1024;    // 2 x 128 fp32 row sums   (1 KB)
constexpr int OPART_B = 2048;    // 128 x OP_STRIDE fp32 partial O (34 KB)
constexpr int OP_STRIDE = 68;
}

__device__ __align__(16) unsigned char g_Wh[2 * 49152];

// ---------------------------------------------------------------------------
static __device__ __forceinline__ uint32_t smem_u32(const void* p) {
    uint32_t a;
    asm("{ .reg .u64 t; cvta.to.shared.u64 t, %1; cvt.u32.u64 %0, t; }" : "=r"(a) : "l"(p));
    return a;
}
static __device__ __forceinline__ uint32_t pkh(float f0, float f1) {
    uint32_t r;
    asm("cvt.rn.f16x2.f32 %0, %1, %2;" : "=r"(r) : "f"(f1), "f"(f0));
    return r;
}
static __device__ __forceinline__ void split2h(float f0, float f1, uint32_t& h, uint32_t& l) {
    h = pkh(f0, f1);
    float g0, g1;
    asm("{.reg .b16 a,b;\n\t mov.b32 {a,b}, %2;\n\t cvt.f32.f16 %0, a;\n\t cvt.f32.f16 %1, b;}"
        : "=f"(g0), "=f"(g1) : "r"(h));
    l = pkh(f0 - g0, f1 - g1);
}
static __device__ __forceinline__ void ldsm4(uint32_t r[4], uint32_t addr) {
    asm volatile("ldmatrix.sync.aligned.m8n8.x4.shared.b16 {%0,%1,%2,%3}, [%4];"
                 : "=r"(r[0]), "=r"(r[1]), "=r"(r[2]), "=r"(r[3]) : "r"(addr));
}
static __device__ __forceinline__ void ldsm4t(uint32_t r[4], uint32_t addr) {
    asm volatile("ldmatrix.sync.aligned.m8n8.x4.trans.shared.b16 {%0,%1,%2,%3}, [%4];"
                 : "=r"(r[0]), "=r"(r[1]), "=r"(r[2]), "=r"(r[3]) : "r"(addr));
}
static __device__ __forceinline__ void mma16816(float d[4],
                                                const uint32_t a[4],
                                                uint32_t b0, uint32_t b1) {
    asm volatile(
        "mma.sync.aligned.m16n8k16.row.col.f32.f16.f16.f32 "
        "{%0,%1,%2,%3}, {%4,%5,%6,%7}, {%8,%9}, {%0,%1,%2,%3};"
        : "+f"(d[0]), "+f"(d[1]), "+f"(d[2]), "+f"(d[3])
        : "r"(a[0]), "r"(a[1]), "r"(a[2]), "r"(a[3]), "r"(b0), "r"(b1));
}
#define CP16(dst, src) \
    asm volatile("cp.async.cg.shared.global [%0], [%1], 16;" :: "r"(dst), "l"(src) : "memory")
#define CPCOMMIT() asm volatile("cp.async.commit_group;" ::: "memory")
#define CPWAIT(n)  asm volatile("cp.async.wait_group %0;" :: "n"(n) : "memory")

// ---------------------------------------------------------------------------
__global__ void build_w_images(const float* __restrict__ Wq,
                               const float* __restrict__ Wk,
                               const float* __restrict__ Wv)
{
    int gid = blockIdx.x * blockDim.x + threadIdx.x;
    int c   = gid / 3072;
    int u   = gid % 3072;
    int n   = u >> 4;
    int j   = u & 15;
    int k0  = c * 128 + j * 8;

    const float* Wsrc = (n < 64) ? (Wq + n) : (n < 128) ? (Wk + n - 64) : (Wv + n - 128);
    float f[8];
    #pragma unroll
    for (int e = 0; e < 8; ++e) f[e] = Wsrc[(size_t)(k0 + e) * cfg::H];

    uint32_t h[4];
    #pragma unroll
    for (int p = 0; p < 4; ++p) h[p] = pkh(f[2 * p], f[2 * p + 1]);

    size_t off = (size_t)c * 49152 + (size_t)n * 256 + (size_t)((j ^ (n & 7)) << 4);
    *(uint4*)(g_Wh + off) = make_uint4(h[0], h[1], h[2], h[3]);
}

// ---------------------------------------------------------------------------
// Main kernel: one CTA (512 threads) handles TWO consecutive batches.
// ---------------------------------------------------------------------------
__global__ __launch_bounds__(512, 1)
void attn_head_kernel(const float* __restrict__ x,
                      float* __restrict__ out)
{
    using namespace cfg;
    extern __shared__ __align__(1024) unsigned char smraw[];
    unsigned char* smc = smraw;
    float*         smp = (float*)smraw;

    const int tid = threadIdx.x;
    const int wid = tid >> 5;
    const int lid = tid & 31;
    const uint32_t sb = smem_u32(smraw);

    // ===== W copies once per CTA (both chunks, hi only) =====
    #pragma unroll
    for (int i = 0; i < 6; ++i) {
        int u = i * 512 + tid;
        CP16(sb + B0HI_B + u * 16, g_Wh + u * 16);
    }
    CPCOMMIT();
    #pragma unroll
    for (int i = 0; i < 6; ++i) {
        int u = i * 512 + tid;
        CP16(sb + B1HI_B + u * 16, g_Wh + 49152 + u * 16);
    }
    CPCOMMIT();

    // ===== Warp-tile constants: 4x4 grid, tile 32x48 =====
    const int mbase = (wid >> 2) * 32;
    const int nbase = (wid & 3) * 48;
    const int arow  = mbase + (lid & 7) + ((lid >> 3) & 1) * 8;
    const int axor  = arow & 7;
    const int ajsel = (lid >> 4) & 1;
    const int brow  = nbase + (lid & 7) + ((lid >> 4) & 1) * 8;
    const int bxor  = brow & 7;
    const int bjsel = (lid >> 3) & 1;

    // Attention constants
    const int pr  = wid & 7;
    const int mem = wid >> 3;
    const int qs  = (pr < 4) ? pr : 11 - pr;
    const int rw  = qs * 16;
    const int rofsA = (lid & 7) + ((lid >> 3) & 1) * 8;
    const int jselA = (lid >> 4) & 1;
    const int rofsK = (lid & 7) + ((lid >> 4) & 1) * 8;
    const int jselK = (lid >> 3) & 1;
    const int xorr  = lid & 7;
    const int vub   = (lid >> 4) & 1;
    const int r0    = lid >> 2;
    const int cq    = (lid & 3) * 2;
    const int rowh  = rw + r0;
    const int rowl  = rowh + 8;
    float* redm = smp + (REDM_B >> 2);
    float* reds = smp + (REDS_B >> 2);
    float* opar = smp + (OPART_B >> 2);

    const uint32_t a0h = sb + A0HI_B + arow * 256;
    const uint32_t a1h = sb + A1HI_B + arow * 256;
    const uint32_t b0  = sb + B0HI_B + brow * 256;
    const uint32_t b1  = sb + B1HI_B + brow * 256;

    #pragma unroll 1
    for (int it2 = 0; it2 < 2; ++it2) {
        const int b = blockIdx.x * 2 + it2;
        const float* xb = x + (size_t)b * (T * E);

        // ===== x chunk 0 -> A0 hi (1-term) =====
        if (it2 == 0) {
            #pragma unroll
            for (int i = 0; i < 4; ++i) {
                int u   = i * 512 + tid;
                int row = u >> 4;
                int j   = u & 15;
                const float4* src = (const float4*)(xb + (size_t)row * E + j * 8);
                float4 fa = src[0], fb = src[1];
                uint32_t h0 = pkh(fa.x, fa.y), h1 = pkh(fa.z, fa.w);
                uint32_t h2 = pkh(fb.x, fb.y), h3 = pkh(fb.z, fb.w);
                int off = row * 256 + ((j ^ (row & 7)) << 4);
                *(uint4*)(smc + A0HI_B + off) = make_uint4(h0, h1, h2, h3);
            }
            CPWAIT(1);   // B0 resident
        } else {
            // chunk 0 was prefetched raw into XRAW during batch-1 attention
            #pragma unroll
            for (int i = 0; i < 4; ++i) {
                int u   = i * 512 + tid;
                int row = u >> 4;
                int j   = u & 15;
                const float4* src = (const float4*)(smc + XRAW_B + row * 512 + j * 32);
                float4 fa = src[0], fb = src[1];
                uint32_t h0 = pkh(fa.x, fa.y), h1 = pkh(fa.z, fa.w);
                uint32_t h2 = pkh(fb.x, fb.y), h3 = pkh(fb.z, fb.w);
                int off = row * 256 + ((j ^ (row & 7)) << 4);
                *(uint4*)(smc + A0HI_B + off) = make_uint4(h0, h1, h2, h3);
            }
        }
        __syncthreads();

        float acc[2][6][4];
        #pragma unroll
        for (int mt = 0; mt < 2; ++mt)
            #pragma unroll
            for (int nt = 0; nt < 6; ++nt)
                #pragma unroll
                for (int r = 0; r < 4; ++r) acc[mt][nt][r] = 0.f;

        // One k16-step: 1-term (hi-only) GEMM
        auto kstep = [&](uint32_t aHi, uint32_t bB, int s) {
            const uint32_t aoff = (uint32_t)(((2 * s + ajsel) ^ axor) << 4);
            const uint32_t boff = (uint32_t)(((2 * s + bjsel) ^ bxor) << 4);
            uint32_t ah[2][4];
            ldsm4(ah[0], aHi + aoff);
            ldsm4(ah[1], aHi + 16 * 256 + aoff);
            #pragma unroll
            for (int g = 0; g < 3; ++g) {
                uint32_t bh[4];
                ldsm4(bh, bB + g * 16 * 256 + boff);
                #pragma unroll
                for (int mt = 0; mt < 2; ++mt)
                    #pragma unroll
                    for (int nn = 0; nn < 2; ++nn)
                        mma16816(acc[mt][g * 2 + nn], ah[mt], bh[g * 0 + 2 * nn], bh[2 * nn + 1]);
            }
        };

        // ===== MMA chunk 0, x chunk-1 convert pipelined on even k-steps =====
        float4 p0, p1;
        {
            int row = tid >> 4, j = tid & 15;
            const float4* src = (const float4*)(xb + (size_t)row * E + 128 + j * 8);
            p0 = src[0]; p1 = src[1];
        }
        #pragma unroll 1
        for (int s = 0; s < 8; ++s) {
            kstep(a0h, b0, s);
            if ((s & 1) == 0) {
                int i = s >> 1;
                int u = i * 512 + tid;
                int row = u >> 4, j = u & 15;
                uint32_t h0 = pkh(p0.x, p0.y), h1 = pkh(p0.z, p0.w);
                uint32_t h2 = pkh(p1.x, p1.y), h3 = pkh(p1.z, p1.w);
                int off = row * 256 + ((j ^ (row & 7)) << 4);
                *(uint4*)(smc + A1HI_B + off) = make_uint4(h0, h1, h2, h3);
                if (i < 3) {
                    int u2 = (i + 1) * 512 + tid;
                    int r2 = u2 >> 4, j2 = u2 & 15;
                    const float4* src = (const float4*)(xb + (size_t)r2 * E + 128 + j2 * 8);
                    p0 = src[0]; p1 = src[1];
                }
            }
        }
        if (it2 == 0) CPWAIT(0);   // B1 resident
        __syncthreads();

        // ===== MMA chunk 1 =====
        #pragma unroll 1
        for (int s = 0; s < 8; ++s) kstep(a1h, b1, s);
        __syncthreads();

        // ===== Epilogue: Q hi+lo (scaled 1/8); K,V hi only =====
        {
            const int er = lid >> 2;
            const int c4 = lid & 3;
            #pragma unroll
            for (int mt = 0; mt < 2; ++mt) {
                #pragma unroll
                for (int nt = 0; nt < 6; ++nt) {
                    int n = nbase + 8 * nt;
                    int row = mbase + mt * 16 + er;
                    int rw8 = row + 8;
                    if (n < 64) {
                        int u = n >> 3;
                        uint32_t h0, l0, h1, l1;
                        split2h(0.125f * acc[mt][nt][0], 0.125f * acc[mt][nt][1], h0, l0);
                        split2h(0.125f * acc[mt][nt][2], 0.125f * acc[mt][nt][3], h1, l1);
                        int byt0 = row * 128 + ((u ^ (row & 7)) << 4) + c4 * 4;
                        int byt1 = rw8 * 128 + ((u ^ (rw8 & 7)) << 4) + c4 * 4;
                        *(uint32_t*)(smc + QHI_B + byt0) = h0;
                        *(uint32_t*)(smc + QLO_B + byt0) = l0;
                        *(uint32_t*)(smc + QHI_B + byt1) = h1;
                        *(uint32_t*)(smc + QLO_B + byt1) = l1;
                    } else {
                        int hiB = (n < 128) ? KHI_B : VHI_B;
                        int m   = (n < 128) ? n - 64 : n - 128;
                        int u   = m >> 3;
                        uint32_t h0 = pkh(acc[mt][nt][0], acc[mt][nt][1]);
                        uint32_t h1 = pkh(acc[mt][nt][2], acc[mt][nt][3]);
                        int byt0 = row * 128 + ((u ^ (row & 7)) << 4) + c4 * 4;
                        int byt1 = rw8 * 128 + ((u ^ (rw8 & 7)) << 4) + c4 * 4;
                        *(uint32_t*)(smc + hiB + byt0) = h0;
                        *(uint32_t*)(smc + hiB + byt1) = h1;
                    }
                }
            }
        }
        __syncthreads();

        // ===== Attention: Q frags first, then barrier (scratch overlays Q) =====
        uint32_t qh[4][4], ql[4][4];
        #pragma unroll
        for (int s = 0; s < 4; ++s) {
            uint32_t off = (uint32_t)((rw + rofsA) * 128 + (((2 * s + jselA) ^ xorr) << 4));
            ldsm4(qh[s], sb + QHI_B + off);
            ldsm4(ql[s], sb + QLO_B + off);
        }
        __syncthreads();

        // Prefetch next batch's raw x chunk0 into XRAW (dead A region)
        if (it2 == 0) {
            const float* xn = x + (size_t)(b + 1) * (T * E);
            #pragma unroll
            for (int i = 0; i < 8; ++i) {
                int u   = i * 512 + tid;
                int row = u >> 5;
                int j2  = u & 31;
                CP16(sb + XRAW_B + u * 16, xn + (size_t)row * E + j2 * 4);
            }
            CPCOMMIT();
        }

        float sacc[4][2][4];
        #pragma unroll
        for (int itk = 0; itk < 4; ++itk)
            #pragma unroll
            for (int nn = 0; nn < 2; ++nn)
                #pragma unroll
                for (int i = 0; i < 4; ++i) sacc[itk][nn][i] = 0.f;

        #pragma unroll
        for (int itk = 0; itk < 4; ++itk) {
            int pb = 2 * itk + mem;
            if (pb <= qs) {
                #pragma unroll
                for (int s = 0; s < 4; ++s) {
                    uint32_t off = (uint32_t)((16 * pb + rofsK) * 128 +
                                              (((2 * s + jselK) ^ xorr) << 4));
                    uint32_t kh[4];
                    ldsm4(kh, sb + KHI_B + off);
                    #pragma unroll
                    for (int nn = 0; nn < 2; ++nn) {
                        mma16816(sacc[itk][nn], qh[s], kh[2 * nn], kh[2 * nn + 1]);
                        mma16816(sacc[itk][nn], ql[s], kh[2 * nn], kh[2 * nn + 1]);
                    }
                }
            }
        }

        float m0 = -1e30f, m1 = -1e30f;
        #pragma unroll
        for (int itk = 0; itk < 4; ++itk) {
            int pb = 2 * itk + mem;
            if (pb <= qs) {
                #pragma unroll
                for (int nn = 0; nn < 2; ++nn) {
                    if (pb == qs) {
                        int colb = 16 * pb + 8 * nn + cq;
                        if (colb     > rowh) sacc[itk][nn][0] = -1e30f;
                        if (colb + 1 > rowh) sacc[itk][nn][1] = -1e30f;
                        if (colb     > rowl) sacc[itk][nn][2] = -1e30f;
                        if (colb + 1 > rowl) sacc[itk][nn][3] = -1e30f;
                    }
                    m0 = fmaxf(m0, fmaxf(sacc[itk][nn][0], sacc[itk][nn][1]));
                    m1 = fmaxf(m1, fmaxf(sacc[itk][nn][2], sacc[itk][nn][3]));
                }
            }
        }
        m0 = fmaxf(m0, __shfl_xor_sync(0xffffffffu, m0, 1));
        m0 = fmaxf(m0, __shfl_xor_sync(0xffffffffu, m0, 2));
        m1 = fmaxf(m1, __shfl_xor_sync(0xffffffffu, m1, 1));
        m1 = fmaxf(m1, __shfl_xor_sync(0xffffffffu, m1, 2));
        if ((lid & 3) == 0) {
            redm[mem * 128 + rowh] = m0;
            redm[mem * 128 + rowl] = m1;
        }
        __syncthreads();
        const float mx0 = fmaxf(redm[rowh], redm[128 + rowh]);
        const float mx1 = fmaxf(redm[rowl], redm[128 + rowl]);

        float s0 = 0.f, s1 = 0.f;
        #pragma unroll
        for (int itk = 0; itk < 4; ++itk) {
            int pb = 2 * itk + mem;
            if (pb <= qs) {
                #pragma unroll
                for (int nn = 0; nn < 2; ++nn) {
                    sacc[itk][nn][0] = __expf(sacc[itk][nn][0] - mx0);
                    sacc[itk][nn][1] = __expf(sacc[itk][nn][1] - mx0);
                    sacc[itk][nn][2] = __expf(sacc[itk][nn][2] - mx1);
                    sacc[itk][nn][3] = __expf(sacc[itk][nn][3] - mx1);
                    s0 += sacc[itk][nn][0] + sacc[itk][nn][1];
                    s1 += sacc[itk][nn][2] + sacc[itk][nn][3];
                }
            }
        }
        s0 += __shfl_xor_sync(0xffffffffu, s0, 1);
        s0 += __shfl_xor_sync(0xffffffffu, s0, 2);
        s1 += __shfl_xor_sync(0xffffffffu, s1, 1);
        s1 += __shfl_xor_sync(0xffffffffu, s1, 2);
        if ((lid & 3) == 0) {
            reds[mem * 128 + rowh] = s0;
            reds[mem * 128 + rowl] = s1;
        }

        uint32_t ph[4][4], pl[4][4];
        #pragma unroll
        for (int itk = 0; itk < 4; ++itk) {
            int pb = 2 * itk + mem;
            if (pb <= qs) {
                split2h(sacc[itk][0][0], sacc[itk][0][1], ph[itk][0], pl[itk][0]);
                split2h(sacc[itk][0][2], sacc[itk][0][3], ph[itk][1], pl[itk][1]);
                split2h(sacc[itk][1][0], sacc[itk][1][1], ph[itk][2], pl[itk][2]);
                split2h(sacc[itk][1][2], sacc[itk][1][3], ph[itk][3], pl[itk][3]);
            }
        }

        float oacc[8][4];
        #pragma unroll
        for (int nb = 0; nb < 8; ++nb)
            #pragma unroll
            for (int i = 0; i < 4; ++i) oacc[nb][i] = 0.f;

        #pragma unroll
        for (int itk = 0; itk < 4; ++itk) {
            int pb = 2 * itk + mem;
            if (pb <= qs) {
                #pragma unroll
                for (int cg = 0; cg < 4; ++cg) {
                    uint32_t off = (uint32_t)((16 * pb + rofsA) * 128 +
                                              (((2 * cg + vub) ^ xorr) << 4));
                    uint32_t vh[4];
                    ldsm4t(vh, sb + VHI_B + off);
                    #pragma unroll
                    for (int nn = 0; nn < 2; ++nn) {
                        mma16816(oacc[2 * cg + nn], ph[itk], vh[2 * nn], vh[2 * nn + 1]);
                        mma16816(oacc[2 * cg + nn], pl[itk], vh[2 * nn], vh[2 * nn + 1]);
                    }
                }
            }
        }

        if (mem == 0) {
            #pragma unroll
            for (int nb = 0; nb < 8; ++nb) {
                int col = 8 * nb + cq;
                float2 v0; v0.x = oacc[nb][0]; v0.y = oacc[nb][1];
                float2 v1; v1.x = oacc[nb][2]; v1.y = oacc[nb][3];
                *(float2*)(opar + rowh * OP_STRIDE + col) = v0;
                *(float2*)(opar + rowl * OP_STRIDE + col) = v1;
            }
        }
        __syncthreads();
        if (mem == 1) {
            const float inv0 = 1.f / (reds[rowh] + reds[128 + rowh]);
            const float inv1 = 1.f / (reds[rowl] + reds[128 + rowl]);
            float* ob = out + (size_t)b * T * H;
            #pragma unroll
            for (int nb = 0; nb < 8; ++nb) {
                int col = 8 * nb + cq;
                float2 u0 = *(float2*)(opar + rowh * OP_STRIDE + col);
                float2 u1 = *(float2*)(opar + rowl * OP_STRIDE + col);
                float2 v0; v0.x = (oacc[nb][0] + u0.x) * inv0; v0.y = (oacc[nb][1] + u0.y) * inv0;
                float2 v1; v1.x = (oacc[nb][2] + u1.x) * inv1; v1.y = (oacc[nb][3] + u1.y) * inv1;
                *(float2*)(ob + rowh * H + col) = v0;
                *(float2*)(ob + rowl * H + col) = v1;
            }
        }
        CPWAIT(0);       // raw-x prefetch complete (cross-thread data)
        __syncthreads(); // visibility + region reuse safety for next batch
    }
}

// ---------------------------------------------------------------------------
extern "C" void kernel_launch(void* const* d_in, const int* in_sizes, int n_in,
                              void* d_out, int out_size)
{
    using namespace cfg;
    const float* x  = (const float*)d_in[0];
    const float* Wq = (const float*)d_in[1];
    const float* Wk = (const float*)d_in[2];
    const float* Wv = (const float*)d_in[3];
    float* out = (float*)d_out;

    const int B = in_sizes[0] / (T * E);

    build_w_images<<<24, 256>>>(Wq, Wk, Wv);

    cudaFuncSetAttribute(attn_head_kernel,
                         cudaFuncAttributeMaxDynamicSharedMemorySize, SMEM_BYTES);
    attn_head_kernel<<<B / 2, 512, SMEM_BYTES>>>(x, out);
}